// round 14
// baseline (speedup 1.0000x reference)
#include <cuda_runtime.h>
#include <cuda_fp16.h>
#include <cstdint>
#include <cstddef>

// Problem constants
#define Bsz  32
#define Rn   16384
#define Cn   16
#define Od   16

#define WARPS 8
#define RPW   32                  // r per warp in route (each warp: all 32 b)
#define RBLK  (WARPS * RPW)       // 256 r per block
#define PRPW  32                  // r per warp in prep
#define PRBLK (WARPS * PRPW)      // 256 r per prep block

#define PRE   6                   // cp.async prefetch distance
#define SLOTS 8                   // smem ring slots per warp

#define LOG2E 1.4426950408889634f

// K-permutation: logical i mapped so lane (g,tg) owns i=4tg..4tg+3 for both
// A (x) and B (W) fragments — dot products unchanged.

// ---------------- scratch (device globals; no allocation allowed) ----------
__device__ uint4 g_Wh4[(size_t)Rn * Cn * 32 + 32];  // 134 MB fp16 W, frag-packed
__device__ float g_Wsum[Cn * 256];              // sum over r of W  [c][o][i]
__device__ float g_v0[Bsz * Cn * Od];
__device__ float g_vsum[Bsz * Cn * Od];         // v0 + v1
__device__ float g_sraw[Bsz * Cn * Od];         // un-normalized weighted sums
__device__ float g_sumexp[Bsz * Cn];            // sum of exp(logit) per (b,c)

// ---------------- helpers ---------------------------------------------------
__device__ __forceinline__ uint32_t packh2(float a, float b) {
    __half2 h = __floats2half2_rn(a, b);
    return *reinterpret_cast<uint32_t*>(&h);
}

union F2U { float2 f; unsigned long long u; };

__device__ __forceinline__ float2 ffma2(float2 a, float2 b, float2 c) {
    F2U A, B, C, D; A.f = a; B.f = b; C.f = c;
    asm("fma.rn.f32x2 %0, %1, %2, %3;" : "=l"(D.u) : "l"(A.u), "l"(B.u), "l"(C.u));
    return D.f;
}
__device__ __forceinline__ float2 fmul2(float2 a, float2 b) {
    F2U A, B, D; A.f = a; B.f = b;
    asm("mul.rn.f32x2 %0, %1, %2;" : "=l"(D.u) : "l"(A.u), "l"(B.u));
    return D.f;
}
__device__ __forceinline__ float2 fadd2(float2 a, float2 b) {
    F2U A, B, D; A.f = a; B.f = b;
    asm("add.rn.f32x2 %0, %1, %2;" : "=l"(D.u) : "l"(A.u), "l"(B.u));
    return D.f;
}

__device__ __forceinline__ uint32_t smem_u32(const void* p) {
    return (uint32_t)__cvta_generic_to_shared(p);
}
__device__ __forceinline__ void cp_async16(uint32_t saddr, const void* gptr) {
    asm volatile("cp.async.cg.shared.global [%0], [%1], 16;\n"
                 :: "r"(saddr), "l"(gptr));
}
__device__ __forceinline__ void cp_commit() {
    asm volatile("cp.async.commit_group;\n");
}
template <int N>
__device__ __forceinline__ void cp_wait() {
    asm volatile("cp.async.wait_group %0;\n" :: "n"(N));
}

// mma m16n8k16: dA = rows g (b-low), dB = rows g+8 (b-high), cols = 2 o's
__device__ __forceinline__ void mma16816(float2& dA, float2& dB, const uint32_t* a,
                                         uint32_t b0, uint32_t b1) {
    asm volatile(
        "mma.sync.aligned.m16n8k16.row.col.f32.f16.f16.f32 "
        "{%0,%1,%2,%3}, {%4,%5,%6,%7}, {%8,%9}, {%10,%11,%12,%13};\n"
        : "=f"(dA.x), "=f"(dA.y), "=f"(dB.x), "=f"(dB.y)
        : "r"(a[0]), "r"(a[1]), "r"(a[2]), "r"(a[3]),
          "r"(b0), "r"(b1),
          "f"(0.f), "f"(0.f), "f"(0.f), "f"(0.f));
}

// ---------------- K0: zero accumulators (per replay) -----------------------
__global__ void k_zero() {
    int i = blockIdx.x * blockDim.x + threadIdx.x;
    if (i < Cn * 256)       g_Wsum[i] = 0.f;
    if (i < Bsz * Cn * Od)  g_sraw[i] = 0.f;
    if (i < Bsz * Cn)       g_sumexp[i] = 0.f;
}

// ---------------- K1: prep — convert W to packed fp16 frags + Wsum ---------
// K-permuted: lane (g,tg) loads W[o=g][4tg..] and W[o=g+8][4tg..] as float4.
// Column sums kept as packed f32x2 (4 add2 instead of 8 FADD per iter).
__global__ __launch_bounds__(256) void k_prep(const float* __restrict__ W) {
    const int c    = blockIdx.y;
    const int tid  = threadIdx.x;
    const int wid  = tid >> 5;
    const int lane = tid & 31;
    const int g    = lane >> 2;
    const int tg   = lane & 3;
    const int r0   = blockIdx.x * PRBLK + wid * PRPW;

    float2 ws2[4];
#pragma unroll
    for (int j = 0; j < 4; j++) ws2[j] = make_float2(0.f, 0.f);

#pragma unroll 16
    for (int k = 0; k < PRPW; k++) {
        const float4* row = reinterpret_cast<const float4*>(
            &W[((size_t)(r0 + k) * Cn + c) * 256]);
        float4 f0 = __ldcs(&row[g * 4 + tg]);          // W[o=g  ][4tg..4tg+3]
        float4 f1 = __ldcs(&row[(g + 8) * 4 + tg]);    // W[o=g+8][4tg..4tg+3]
        ws2[0] = fadd2(ws2[0], make_float2(f0.x, f0.y));
        ws2[1] = fadd2(ws2[1], make_float2(f0.z, f0.w));
        ws2[2] = fadd2(ws2[2], make_float2(f1.x, f1.y));
        ws2[3] = fadd2(ws2[3], make_float2(f1.z, f1.w));
        uint4 o;
        o.x = packh2(f0.x, f0.y); o.y = packh2(f0.z, f0.w);
        o.z = packh2(f1.x, f1.y); o.w = packh2(f1.z, f1.w);
        g_Wh4[((size_t)c * Rn + (r0 + k)) * 32 + lane] = o;
    }

    // fold Wsum partials: lane (g,tg) covers (o=g,i=4tg..) and (o=g+8,i=4tg..)
    __shared__ float s_ws[WARPS][256];
    const int p0 = g * 16 + 4 * tg;
    const int p2 = (g + 8) * 16 + 4 * tg;
    s_ws[wid][p0]     = ws2[0].x; s_ws[wid][p0 + 1] = ws2[0].y;
    s_ws[wid][p0 + 2] = ws2[1].x; s_ws[wid][p0 + 3] = ws2[1].y;
    s_ws[wid][p2]     = ws2[2].x; s_ws[wid][p2 + 1] = ws2[2].y;
    s_ws[wid][p2 + 2] = ws2[3].x; s_ws[wid][p2 + 3] = ws2[3].y;
    __syncthreads();
    float s = 0.f;
#pragma unroll
    for (int w = 0; w < WARPS; w++) s += s_ws[w][tid];
    atomicAdd(&g_Wsum[c * 256 + tid], s);
}

// ---------------- K2: v0 = squash((1/R) * Wsum . x) ------------------------
__global__ void k_v0(const float* __restrict__ x) {
    int t = blockIdx.x * blockDim.x + threadIdx.x;
    if (t >= Bsz * Cn) return;
    const int b = t >> 4, c = t & 15;
    float s[16], n2 = 0.f;
#pragma unroll
    for (int o = 0; o < 16; o++) {
        float acc = 0.f;
#pragma unroll
        for (int i = 0; i < 16; i++)
            acc = fmaf(g_Wsum[(c * 16 + o) * 16 + i], x[(b * Cn + c) * 16 + i], acc);
        acc *= (1.f / (float)Rn);
        s[o] = acc; n2 += acc * acc;
    }
    const float norm = sqrtf(n2);
    const float sc = norm / (1.f + n2);
#pragma unroll
    for (int o = 0; o < 16; o++) g_v0[t * 16 + o] = sc * s[o];
}

// ---------------- K3: fused routing pass (HMMA + cp.async, all-b warps) -----
// ONE warp handles all 32 b per r. vv2 pre-scaled by log2(e): weight=exp2f(p).
// NO register cap beyond 3 blocks/SM — the working set is ~80 regs (verified);
// forcing lower spills (R7/R12).
__global__ __launch_bounds__(256, 3) void k_route_mma(const float* __restrict__ x,
                                                      const float* __restrict__ vsrc) {
    __shared__ __align__(16) uint4 s_w[WARPS][SLOTS][32];

    const int c    = blockIdx.y;
    const int tid  = threadIdx.x;
    const int wid  = tid >> 5;
    const int lane = tid & 31;
    const int g    = lane >> 2;
    const int tg   = lane & 3;

    // ---- A fragments (all 32 b) + v pairs (pre-scaled by log2e) ----
    uint32_t A[8];
    float2 vv2[8];
#pragma unroll
    for (int h = 0; h < 2; h++) {
        const int b_lo = 16 * h + g, b_hi = 16 * h + 8 + g;
        float4 flo = *reinterpret_cast<const float4*>(&x[(b_lo * Cn + c) * 16 + 4 * tg]);
        float4 fhi = *reinterpret_cast<const float4*>(&x[(b_hi * Cn + c) * 16 + 4 * tg]);
        A[4 * h + 0] = packh2(flo.x, flo.y);
        A[4 * h + 1] = packh2(fhi.x, fhi.y);
        A[4 * h + 2] = packh2(flo.z, flo.w);
        A[4 * h + 3] = packh2(fhi.z, fhi.w);
        float2 t0 = *reinterpret_cast<const float2*>(&vsrc[(b_lo * Cn + c) * 16 + 2 * tg]);
        float2 t1 = *reinterpret_cast<const float2*>(&vsrc[(b_lo * Cn + c) * 16 + 2 * tg + 8]);
        float2 t2 = *reinterpret_cast<const float2*>(&vsrc[(b_hi * Cn + c) * 16 + 2 * tg]);
        float2 t3 = *reinterpret_cast<const float2*>(&vsrc[(b_hi * Cn + c) * 16 + 2 * tg + 8]);
        vv2[4 * h + 0] = make_float2(t0.x * LOG2E, t0.y * LOG2E);
        vv2[4 * h + 1] = make_float2(t1.x * LOG2E, t1.y * LOG2E);
        vv2[4 * h + 2] = make_float2(t2.x * LOG2E, t2.y * LOG2E);
        vv2[4 * h + 3] = make_float2(t3.x * LOG2E, t3.y * LOG2E);
    }

    float2 acc2[8];
#pragma unroll
    for (int j = 0; j < 8; j++) acc2[j] = make_float2(0.f, 0.f);
    float esum[4];
#pragma unroll
    for (int j = 0; j < 4; j++) esum[j] = 0.f;

    const int r0 = blockIdx.x * RBLK + wid * RPW;
    const uint4* __restrict__ gsrc = g_Wh4 + ((size_t)c * Rn + r0) * 32 + lane;
    const uint32_t sbase = smem_u32(&s_w[wid][0][lane]);

    // ---- pipeline prologue ----
#pragma unroll
    for (int j = 0; j < PRE; j++) {
        cp_async16(sbase + j * 512, gsrc + (size_t)j * 32);
        cp_commit();
    }

#pragma unroll 8
    for (int k = 0; k < RPW; k++) {
        cp_wait<PRE - 1>();                       // slot k ready
        const uint4 cur = s_w[wid][k & (SLOTS - 1)][lane];
        if (k + PRE < RPW)
            cp_async16(sbase + ((k + PRE) & (SLOTS - 1)) * 512,
                       gsrc + (size_t)(k + PRE) * 32);
        cp_commit();                              // one group per iteration

#pragma unroll
        for (int h = 0; h < 2; h++) {
            float2 dA1, dB1, dA2, dB2;
            mma16816(dA1, dB1, A + 4 * h, cur.x, cur.y);   // o 0-7
            mma16816(dA2, dB2, A + 4 * h, cur.z, cur.w);   // o 8-15

            float2 q0 = ffma2(dA2, vv2[4 * h + 1], fmul2(dA1, vv2[4 * h + 0]));
            float2 q1 = ffma2(dB2, vv2[4 * h + 3], fmul2(dB1, vv2[4 * h + 2]));
            float p0 = q0.x + q0.y;
            float p1 = q1.x + q1.y;
            p0 += __shfl_xor_sync(0xffffffffu, p0, 1);
            p0 += __shfl_xor_sync(0xffffffffu, p0, 2);
            p1 += __shfl_xor_sync(0xffffffffu, p1, 1);
            p1 += __shfl_xor_sync(0xffffffffu, p1, 2);

            const float w0 = exp2f(p0);    // = exp(u.v): v pre-scaled by log2e
            const float w1 = exp2f(p1);
            esum[2 * h]     += w0;
            esum[2 * h + 1] += w1;
            const float2 w02 = make_float2(w0, w0);
            const float2 w12 = make_float2(w1, w1);
            acc2[4 * h + 0] = ffma2(w02, dA1, acc2[4 * h + 0]);
            acc2[4 * h + 1] = ffma2(w02, dA2, acc2[4 * h + 1]);
            acc2[4 * h + 2] = ffma2(w12, dB1, acc2[4 * h + 2]);
            acc2[4 * h + 3] = ffma2(w12, dB2, acc2[4 * h + 3]);
        }
    }

    // ---- block reduction ----
    // j16 = 8*h + jj:
    //   b = (ln>>2) + 8*(jj>>2) + 16*h ; o = 2*(ln&3) + (jj&1) + 8*((jj>>1)&1)
    __shared__ float s_acc[WARPS][16][32];
    __shared__ float s_es[WARPS][32];
#pragma unroll
    for (int h = 0; h < 2; h++) {
        s_acc[wid][8*h + 0][lane] = acc2[4*h + 0].x;
        s_acc[wid][8*h + 1][lane] = acc2[4*h + 0].y;
        s_acc[wid][8*h + 2][lane] = acc2[4*h + 1].x;
        s_acc[wid][8*h + 3][lane] = acc2[4*h + 1].y;
        s_acc[wid][8*h + 4][lane] = acc2[4*h + 2].x;
        s_acc[wid][8*h + 5][lane] = acc2[4*h + 2].y;
        s_acc[wid][8*h + 6][lane] = acc2[4*h + 3].x;
        s_acc[wid][8*h + 7][lane] = acc2[4*h + 3].y;
    }
    if (tg == 0) {
        s_es[wid][g]      = esum[0];
        s_es[wid][g + 8]  = esum[1];
        s_es[wid][g + 16] = esum[2];
        s_es[wid][g + 24] = esum[3];
    }
    __syncthreads();

#pragma unroll
    for (int pass = 0; pass < 2; pass++) {
        const int cell = pass * 256 + tid;      // 9 bits: j16(4) lane(5)
        const int j16  = (cell >> 5) & 15;
        const int ln   = cell & 31;
        const int h    = j16 >> 3;
        const int jj   = j16 & 7;
        float s = 0.f;
#pragma unroll
        for (int w2 = 0; w2 < WARPS; w2++) s += s_acc[w2][j16][ln];
        const int b = (ln >> 2) + 8 * (jj >> 2) + 16 * h;
        const int o = ((ln & 3) << 1) + (jj & 1) + 8 * ((jj >> 1) & 1);
        atomicAdd(&g_sraw[(b * Cn + c) * 16 + o], s);
    }
    if (tid < 32) {
        float s = 0.f;
#pragma unroll
        for (int w2 = 0; w2 < WARPS; w2++) s += s_es[w2][tid];
        atomicAdd(&g_sumexp[tid * Cn + c], s);
    }
}

// ---------------- K4: v1 = squash(s1), vsum = v0+v1, reset accumulators ----
__global__ void k_v1() {
    int t = blockIdx.x * blockDim.x + threadIdx.x;
    if (t >= Bsz * Cn) return;
    const float inv = 1.f / g_sumexp[t];
    float s[16], n2 = 0.f;
#pragma unroll
    for (int o = 0; o < 16; o++) { s[o] = g_sraw[t * 16 + o] * inv; n2 += s[o] * s[o]; }
    const float norm = sqrtf(n2);
    const float sc = norm / (1.f + n2);
#pragma unroll
    for (int o = 0; o < 16; o++) {
        g_vsum[t * 16 + o] = g_v0[t * 16 + o] + sc * s[o];
        g_sraw[t * 16 + o] = 0.f;
    }
    g_sumexp[t] = 0.f;
}

// ---------------- K5: out = squash(s2) --------------------------------------
__global__ void k_out(float* __restrict__ out) {
    int t = blockIdx.x * blockDim.x + threadIdx.x;
    if (t >= Bsz * Cn) return;
    const float inv = 1.f / g_sumexp[t];
    float s[16], n2 = 0.f;
#pragma unroll
    for (int o = 0; o < 16; o++) { s[o] = g_sraw[t * 16 + o] * inv; n2 += s[o] * s[o]; }
    const float norm = sqrtf(n2);
    const float sc = norm / (1.f + n2);
#pragma unroll
    for (int o = 0; o < 16; o++) out[t * 16 + o] = sc * s[o];
}

// ---------------- launch ----------------------------------------------------
extern "C" void kernel_launch(void* const* d_in, const int* in_sizes, int n_in,
                              void* d_out, int out_size) {
    const float* x = (const float*)d_in[0];
    const float* W = (const float*)d_in[1];
    if (n_in >= 2 && in_sizes[0] > in_sizes[1]) {  // safety: x is 8192, W is 67M
        x = (const float*)d_in[1];
        W = (const float*)d_in[0];
    }
    float* out = (float*)d_out;

    float* d_v0   = nullptr;
    float* d_vsum = nullptr;
    cudaGetSymbolAddress((void**)&d_v0,   g_v0);
    cudaGetSymbolAddress((void**)&d_vsum, g_vsum);

    k_zero<<<32, 256>>>();
    k_prep<<<dim3(Rn / PRBLK, Cn), 256>>>(W);
    k_v0<<<2, 256>>>(x);

    // iteration 1 (uses v0)
    k_route_mma<<<dim3(Rn / RBLK, Cn), 256>>>(x, d_v0);
    k_v1<<<2, 256>>>();

    // iteration 2 (uses v0+v1)
    k_route_mma<<<dim3(Rn / RBLK, Cn), 256>>>(x, d_vsum);
    k_out<<<2, 256>>>(out);
}

// round 15
// speedup vs baseline: 1.3990x; 1.3990x over previous
#include <cuda_runtime.h>
#include <cuda_fp16.h>
#include <cstdint>
#include <cstddef>

// Problem constants
#define Bsz  32
#define Rn   16384
#define Cn   16
#define Od   16

#define WARPS 8
#define RPW   32                  // r per warp in route (each warp: all 32 b)
#define RBLK  (WARPS * RPW)       // 256 r per block
#define PRPW  32                  // r per warp in prep
#define PRBLK (WARPS * PRPW)      // 256 r per prep block

#define PRE   6                   // cp.async prefetch distance
#define SLOTS 8                   // smem ring slots per warp

#define LOG2E 1.4426950408889634f

// K-permutation: logical i mapped so lane (g,tg) owns i=4tg..4tg+3 for both
// A (x) and B (W) fragments — dot products unchanged.

// ---------------- scratch (device globals; no allocation allowed) ----------
__device__ uint4 g_Wh4[(size_t)Rn * Cn * 32 + 32];  // 134 MB fp16 W, frag-packed
__device__ float g_Wsum[Cn * 256];              // sum over r of W  [c][o][i]
__device__ float g_v0[Bsz * Cn * Od];
__device__ float g_vsum[Bsz * Cn * Od];         // v0 + v1
__device__ float g_sraw[Bsz * Cn * Od];         // un-normalized weighted sums
__device__ float g_sumexp[Bsz * Cn];            // sum of exp(logit) per (b,c)

// ---------------- helpers ---------------------------------------------------
__device__ __forceinline__ uint32_t packh2(float a, float b) {
    __half2 h = __floats2half2_rn(a, b);
    return *reinterpret_cast<uint32_t*>(&h);
}

union F2U { float2 f; unsigned long long u; };

__device__ __forceinline__ float2 ffma2(float2 a, float2 b, float2 c) {
    F2U A, B, C, D; A.f = a; B.f = b; C.f = c;
    asm("fma.rn.f32x2 %0, %1, %2, %3;" : "=l"(D.u) : "l"(A.u), "l"(B.u), "l"(C.u));
    return D.f;
}
__device__ __forceinline__ float2 fmul2(float2 a, float2 b) {
    F2U A, B, D; A.f = a; B.f = b;
    asm("mul.rn.f32x2 %0, %1, %2;" : "=l"(D.u) : "l"(A.u), "l"(B.u));
    return D.f;
}

// Guaranteed single MUFU.EX2 regardless of compile flags (exp2f without
// fast-math expands to the precise libm sequence — R13's regression).
__device__ __forceinline__ float ex2_approx(float x) {
    float r;
    asm("ex2.approx.ftz.f32 %0, %1;" : "=f"(r) : "f"(x));
    return r;
}

__device__ __forceinline__ uint32_t smem_u32(const void* p) {
    return (uint32_t)__cvta_generic_to_shared(p);
}
__device__ __forceinline__ void cp_async16(uint32_t saddr, const void* gptr) {
    asm volatile("cp.async.cg.shared.global [%0], [%1], 16;\n"
                 :: "r"(saddr), "l"(gptr));
}
__device__ __forceinline__ void cp_commit() {
    asm volatile("cp.async.commit_group;\n");
}
template <int N>
__device__ __forceinline__ void cp_wait() {
    asm volatile("cp.async.wait_group %0;\n" :: "n"(N));
}

// mma m16n8k16: dA = rows g (b-low), dB = rows g+8 (b-high), cols = 2 o's
__device__ __forceinline__ void mma16816(float2& dA, float2& dB, const uint32_t* a,
                                         uint32_t b0, uint32_t b1) {
    asm volatile(
        "mma.sync.aligned.m16n8k16.row.col.f32.f16.f16.f32 "
        "{%0,%1,%2,%3}, {%4,%5,%6,%7}, {%8,%9}, {%10,%11,%12,%13};\n"
        : "=f"(dA.x), "=f"(dA.y), "=f"(dB.x), "=f"(dB.y)
        : "r"(a[0]), "r"(a[1]), "r"(a[2]), "r"(a[3]),
          "r"(b0), "r"(b1),
          "f"(0.f), "f"(0.f), "f"(0.f), "f"(0.f));
}

// ---------------- K0: zero accumulators (per replay) -----------------------
__global__ void k_zero() {
    int i = blockIdx.x * blockDim.x + threadIdx.x;
    if (i < Cn * 256)       g_Wsum[i] = 0.f;
    if (i < Bsz * Cn * Od)  g_sraw[i] = 0.f;
    if (i < Bsz * Cn)       g_sumexp[i] = 0.f;
}

// ---------------- K1: prep — convert W to packed fp16 frags + Wsum ---------
// K-permuted: lane (g,tg) loads W[o=g][4tg..] and W[o=g+8][4tg..] as float4.
// (Exact R11 structure — unroll 8, scalar column sums.)
__global__ __launch_bounds__(256) void k_prep(const float* __restrict__ W) {
    const int c    = blockIdx.y;
    const int tid  = threadIdx.x;
    const int wid  = tid >> 5;
    const int lane = tid & 31;
    const int g    = lane >> 2;
    const int tg   = lane & 3;
    const int r0   = blockIdx.x * PRBLK + wid * PRPW;

    float ws[8];
#pragma unroll
    for (int j = 0; j < 8; j++) ws[j] = 0.f;

#pragma unroll 8
    for (int k = 0; k < PRPW; k++) {
        const float4* row = reinterpret_cast<const float4*>(
            &W[((size_t)(r0 + k) * Cn + c) * 256]);
        float4 f0 = __ldcs(&row[g * 4 + tg]);          // W[o=g  ][4tg..4tg+3]
        float4 f1 = __ldcs(&row[(g + 8) * 4 + tg]);    // W[o=g+8][4tg..4tg+3]
        ws[0] += f0.x; ws[1] += f0.y; ws[2] += f0.z; ws[3] += f0.w;
        ws[4] += f1.x; ws[5] += f1.y; ws[6] += f1.z; ws[7] += f1.w;
        uint4 o;
        o.x = packh2(f0.x, f0.y); o.y = packh2(f0.z, f0.w);
        o.z = packh2(f1.x, f1.y); o.w = packh2(f1.z, f1.w);
        g_Wh4[((size_t)c * Rn + (r0 + k)) * 32 + lane] = o;
    }

    // fold Wsum partials: lane (g,tg) covers (o=g,i=4tg..) and (o=g+8,i=4tg..)
    __shared__ float s_ws[WARPS][256];
    const int p0 = g * 16 + 4 * tg;
    const int p2 = (g + 8) * 16 + 4 * tg;
    s_ws[wid][p0]     = ws[0]; s_ws[wid][p0 + 1] = ws[1];
    s_ws[wid][p0 + 2] = ws[2]; s_ws[wid][p0 + 3] = ws[3];
    s_ws[wid][p2]     = ws[4]; s_ws[wid][p2 + 1] = ws[5];
    s_ws[wid][p2 + 2] = ws[6]; s_ws[wid][p2 + 3] = ws[7];
    __syncthreads();
    float s = 0.f;
#pragma unroll
    for (int w = 0; w < WARPS; w++) s += s_ws[w][tid];
    atomicAdd(&g_Wsum[c * 256 + tid], s);
}

// ---------------- K2: v0 = squash((1/R) * Wsum . x) ------------------------
__global__ void k_v0(const float* __restrict__ x) {
    int t = blockIdx.x * blockDim.x + threadIdx.x;
    if (t >= Bsz * Cn) return;
    const int b = t >> 4, c = t & 15;
    float s[16], n2 = 0.f;
#pragma unroll
    for (int o = 0; o < 16; o++) {
        float acc = 0.f;
#pragma unroll
        for (int i = 0; i < 16; i++)
            acc = fmaf(g_Wsum[(c * 16 + o) * 16 + i], x[(b * Cn + c) * 16 + i], acc);
        acc *= (1.f / (float)Rn);
        s[o] = acc; n2 += acc * acc;
    }
    const float norm = sqrtf(n2);
    const float sc = norm / (1.f + n2);
#pragma unroll
    for (int o = 0; o < 16; o++) g_v0[t * 16 + o] = sc * s[o];
}

// ---------------- K3: fused routing pass (HMMA + cp.async, all-b warps) -----
// Exact R11 structure (80 regs, 3 blocks/SM). vv2 pre-scaled by log2e; weight
// via raw ex2.approx (one MUFU — one FMUL fewer than __expf).
__global__ __launch_bounds__(256, 3) void k_route_mma(const float* __restrict__ x,
                                                      const float* __restrict__ vsrc) {
    __shared__ __align__(16) uint4 s_w[WARPS][SLOTS][32];

    const int c    = blockIdx.y;
    const int tid  = threadIdx.x;
    const int wid  = tid >> 5;
    const int lane = tid & 31;
    const int g    = lane >> 2;
    const int tg   = lane & 3;

    // ---- A fragments (all 32 b) + v pairs (pre-scaled by log2e) ----
    uint32_t A[8];
    float2 vv2[8];
#pragma unroll
    for (int h = 0; h < 2; h++) {
        const int b_lo = 16 * h + g, b_hi = 16 * h + 8 + g;
        float4 flo = *reinterpret_cast<const float4*>(&x[(b_lo * Cn + c) * 16 + 4 * tg]);
        float4 fhi = *reinterpret_cast<const float4*>(&x[(b_hi * Cn + c) * 16 + 4 * tg]);
        A[4 * h + 0] = packh2(flo.x, flo.y);
        A[4 * h + 1] = packh2(fhi.x, fhi.y);
        A[4 * h + 2] = packh2(flo.z, flo.w);
        A[4 * h + 3] = packh2(fhi.z, fhi.w);
        float2 t0 = *reinterpret_cast<const float2*>(&vsrc[(b_lo * Cn + c) * 16 + 2 * tg]);
        float2 t1 = *reinterpret_cast<const float2*>(&vsrc[(b_lo * Cn + c) * 16 + 2 * tg + 8]);
        float2 t2 = *reinterpret_cast<const float2*>(&vsrc[(b_hi * Cn + c) * 16 + 2 * tg]);
        float2 t3 = *reinterpret_cast<const float2*>(&vsrc[(b_hi * Cn + c) * 16 + 2 * tg + 8]);
        vv2[4 * h + 0] = make_float2(t0.x * LOG2E, t0.y * LOG2E);
        vv2[4 * h + 1] = make_float2(t1.x * LOG2E, t1.y * LOG2E);
        vv2[4 * h + 2] = make_float2(t2.x * LOG2E, t2.y * LOG2E);
        vv2[4 * h + 3] = make_float2(t3.x * LOG2E, t3.y * LOG2E);
    }

    float2 acc2[8];
#pragma unroll
    for (int j = 0; j < 8; j++) acc2[j] = make_float2(0.f, 0.f);
    float esum[4];
#pragma unroll
    for (int j = 0; j < 4; j++) esum[j] = 0.f;

    const int r0 = blockIdx.x * RBLK + wid * RPW;
    const uint4* __restrict__ gsrc = g_Wh4 + ((size_t)c * Rn + r0) * 32 + lane;
    const uint32_t sbase = smem_u32(&s_w[wid][0][lane]);

    // ---- pipeline prologue ----
#pragma unroll
    for (int j = 0; j < PRE; j++) {
        cp_async16(sbase + j * 512, gsrc + (size_t)j * 32);
        cp_commit();
    }

#pragma unroll 8
    for (int k = 0; k < RPW; k++) {
        cp_wait<PRE - 1>();                       // slot k ready
        const uint4 cur = s_w[wid][k & (SLOTS - 1)][lane];
        if (k + PRE < RPW)
            cp_async16(sbase + ((k + PRE) & (SLOTS - 1)) * 512,
                       gsrc + (size_t)(k + PRE) * 32);
        cp_commit();                              // one group per iteration

#pragma unroll
        for (int h = 0; h < 2; h++) {
            float2 dA1, dB1, dA2, dB2;
            mma16816(dA1, dB1, A + 4 * h, cur.x, cur.y);   // o 0-7
            mma16816(dA2, dB2, A + 4 * h, cur.z, cur.w);   // o 8-15

            float2 q0 = ffma2(dA2, vv2[4 * h + 1], fmul2(dA1, vv2[4 * h + 0]));
            float2 q1 = ffma2(dB2, vv2[4 * h + 3], fmul2(dB1, vv2[4 * h + 2]));
            float p0 = q0.x + q0.y;
            float p1 = q1.x + q1.y;
            p0 += __shfl_xor_sync(0xffffffffu, p0, 1);
            p0 += __shfl_xor_sync(0xffffffffu, p0, 2);
            p1 += __shfl_xor_sync(0xffffffffu, p1, 1);
            p1 += __shfl_xor_sync(0xffffffffu, p1, 2);

            const float w0 = ex2_approx(p0);   // = exp(u.v): v pre-scaled
            const float w1 = ex2_approx(p1);
            esum[2 * h]     += w0;
            esum[2 * h + 1] += w1;
            const float2 w02 = make_float2(w0, w0);
            const float2 w12 = make_float2(w1, w1);
            acc2[4 * h + 0] = ffma2(w02, dA1, acc2[4 * h + 0]);
            acc2[4 * h + 1] = ffma2(w02, dA2, acc2[4 * h + 1]);
            acc2[4 * h + 2] = ffma2(w12, dB1, acc2[4 * h + 2]);
            acc2[4 * h + 3] = ffma2(w12, dB2, acc2[4 * h + 3]);
        }
    }

    // ---- block reduction ----
    // j16 = 8*h + jj:
    //   b = (ln>>2) + 8*(jj>>2) + 16*h ; o = 2*(ln&3) + (jj&1) + 8*((jj>>1)&1)
    __shared__ float s_acc[WARPS][16][32];
    __shared__ float s_es[WARPS][32];
#pragma unroll
    for (int h = 0; h < 2; h++) {
        s_acc[wid][8*h + 0][lane] = acc2[4*h + 0].x;
        s_acc[wid][8*h + 1][lane] = acc2[4*h + 0].y;
        s_acc[wid][8*h + 2][lane] = acc2[4*h + 1].x;
        s_acc[wid][8*h + 3][lane] = acc2[4*h + 1].y;
        s_acc[wid][8*h + 4][lane] = acc2[4*h + 2].x;
        s_acc[wid][8*h + 5][lane] = acc2[4*h + 2].y;
        s_acc[wid][8*h + 6][lane] = acc2[4*h + 3].x;
        s_acc[wid][8*h + 7][lane] = acc2[4*h + 3].y;
    }
    if (tg == 0) {
        s_es[wid][g]      = esum[0];
        s_es[wid][g + 8]  = esum[1];
        s_es[wid][g + 16] = esum[2];
        s_es[wid][g + 24] = esum[3];
    }
    __syncthreads();

#pragma unroll
    for (int pass = 0; pass < 2; pass++) {
        const int cell = pass * 256 + tid;      // 9 bits: j16(4) lane(5)
        const int j16  = (cell >> 5) & 15;
        const int ln   = cell & 31;
        const int h    = j16 >> 3;
        const int jj   = j16 & 7;
        float s = 0.f;
#pragma unroll
        for (int w2 = 0; w2 < WARPS; w2++) s += s_acc[w2][j16][ln];
        const int b = (ln >> 2) + 8 * (jj >> 2) + 16 * h;
        const int o = ((ln & 3) << 1) + (jj & 1) + 8 * ((jj >> 1) & 1);
        atomicAdd(&g_sraw[(b * Cn + c) * 16 + o], s);
    }
    if (tid < 32) {
        float s = 0.f;
#pragma unroll
        for (int w2 = 0; w2 < WARPS; w2++) s += s_es[w2][tid];
        atomicAdd(&g_sumexp[tid * Cn + c], s);
    }
}

// ---------------- K4: v1 = squash(s1), vsum = v0+v1, reset accumulators ----
__global__ void k_v1() {
    int t = blockIdx.x * blockDim.x + threadIdx.x;
    if (t >= Bsz * Cn) return;
    const float inv = 1.f / g_sumexp[t];
    float s[16], n2 = 0.f;
#pragma unroll
    for (int o = 0; o < 16; o++) { s[o] = g_sraw[t * 16 + o] * inv; n2 += s[o] * s[o]; }
    const float norm = sqrtf(n2);
    const float sc = norm / (1.f + n2);
#pragma unroll
    for (int o = 0; o < 16; o++) {
        g_vsum[t * 16 + o] = g_v0[t * 16 + o] + sc * s[o];
        g_sraw[t * 16 + o] = 0.f;
    }
    g_sumexp[t] = 0.f;
}

// ---------------- K5: out = squash(s2) --------------------------------------
__global__ void k_out(float* __restrict__ out) {
    int t = blockIdx.x * blockDim.x + threadIdx.x;
    if (t >= Bsz * Cn) return;
    const float inv = 1.f / g_sumexp[t];
    float s[16], n2 = 0.f;
#pragma unroll
    for (int o = 0; o < 16; o++) { s[o] = g_sraw[t * 16 + o] * inv; n2 += s[o] * s[o]; }
    const float norm = sqrtf(n2);
    const float sc = norm / (1.f + n2);
#pragma unroll
    for (int o = 0; o < 16; o++) out[t * 16 + o] = sc * s[o];
}

// ---------------- launch ----------------------------------------------------
extern "C" void kernel_launch(void* const* d_in, const int* in_sizes, int n_in,
                              void* d_out, int out_size) {
    const float* x = (const float*)d_in[0];
    const float* W = (const float*)d_in[1];
    if (n_in >= 2 && in_sizes[0] > in_sizes[1]) {  // safety: x is 8192, W is 67M
        x = (const float*)d_in[1];
        W = (const float*)d_in[0];
    }
    float* out = (float*)d_out;

    float* d_v0   = nullptr;
    float* d_vsum = nullptr;
    cudaGetSymbolAddress((void**)&d_v0,   g_v0);
    cudaGetSymbolAddress((void**)&d_vsum, g_vsum);

    k_zero<<<32, 256>>>();
    k_prep<<<dim3(Rn / PRBLK, Cn), 256>>>(W);
    k_v0<<<2, 256>>>(x);

    // iteration 1 (uses v0)
    k_route_mma<<<dim3(Rn / RBLK, Cn), 256>>>(x, d_v0);
    k_v1<<<2, 256>>>();

    // iteration 2 (uses v0+v1)
    k_route_mma<<<dim3(Rn / RBLK, Cn), 256>>>(x, d_vsum);
    k_out<<<2, 256>>>(out);
}